// round 8
// baseline (speedup 1.0000x reference)
#include <cuda_runtime.h>
#include <math.h>

// ---------------------------------------------------------------------------
// SwinTransformerBlock  B=16, C=384, H=W=64, WS=8, SHIFT=4, HEADS=8, hd=48
// 65536 tokens. GEMMs on tensor cores (tf32 mma.sync), rest fp32.
// Round 7: GEMM v2 — 256x128 block tile, 64x64 warp tile (1.0 LDS/MMA).
// ---------------------------------------------------------------------------

// Scratch (device globals; no runtime allocation)
__device__ float g_ln1[25165824];    // 65536*384   LN1 output, window-ordered
__device__ float g_qkv[75497472];    // 65536*1152  QKV output, window-ordered
__device__ float g_att[25165824];    // 65536*384   attn output, NATURAL order
__device__ float g_xc [25165824];    // 65536*384   proj output (xc), natural
__device__ float g_ln2[25165824];    // 65536*384   LN2 output
__device__ float g_hid[100663296];   // 65536*1536  MLP hidden
__device__ float g_t  [25165824];    // 65536*384   MLP output (t)

template<int ID> __device__ __forceinline__ float* gbuf();
template<> __device__ __forceinline__ float* gbuf<0>() { return g_ln1; }
template<> __device__ __forceinline__ float* gbuf<1>() { return g_qkv; }
template<> __device__ __forceinline__ float* gbuf<2>() { return g_att; }
template<> __device__ __forceinline__ float* gbuf<3>() { return g_xc;  }
template<> __device__ __forceinline__ float* gbuf<4>() { return g_ln2; }
template<> __device__ __forceinline__ float* gbuf<5>() { return g_hid; }
template<> __device__ __forceinline__ float* gbuf<6>() { return g_t;   }

__device__ __forceinline__ unsigned f2tf(float f) {
    unsigned u;
    asm("cvt.rna.tf32.f32 %0, %1;" : "=r"(u) : "f"(f));
    return u;
}

__device__ __forceinline__ void mma_tf32(float c[4], const unsigned a[4], const unsigned b[2]) {
    asm volatile(
        "mma.sync.aligned.m16n8k8.row.col.f32.tf32.tf32.f32 "
        "{%0,%1,%2,%3}, {%4,%5,%6,%7}, {%8,%9}, {%0,%1,%2,%3};"
        : "+f"(c[0]), "+f"(c[1]), "+f"(c[2]), "+f"(c[3])
        : "r"(a[0]), "r"(a[1]), "r"(a[2]), "r"(a[3]), "r"(b[0]), "r"(b[1]));
}

// ---------------------------------------------------------------------------
// Kernel 1: shift + window partition + LayerNorm1 (unchanged)
// ---------------------------------------------------------------------------
__global__ void __launch_bounds__(256) ln1_kernel(const float* __restrict__ x,
                                                  const float* __restrict__ gamma,
                                                  const float* __restrict__ beta) {
    const int bh = blockIdx.x;
    const int b = bh >> 6, h = bh & 63;
    const int t = threadIdx.x;
    const int tok = t & 63, grp = t >> 6;
    const float* base = x + (size_t)b * 384 * 4096 + h * 64;

    float s = 0.f, q = 0.f;
    for (int c = grp * 96; c < grp * 96 + 96; ++c) {
        float v = base[(size_t)c * 4096 + tok];
        s += v; q += v * v;
    }
    __shared__ float ssum[4][64], ssq[4][64];
    __shared__ float smean[64], srstd[64];
    ssum[grp][tok] = s; ssq[grp][tok] = q;
    __syncthreads();
    if (t < 64) {
        float S = ssum[0][t] + ssum[1][t] + ssum[2][t] + ssum[3][t];
        float Q = ssq [0][t] + ssq [1][t] + ssq [2][t] + ssq [3][t];
        float m = S * (1.f / 384.f);
        float v = Q * (1.f / 384.f) - m * m;
        smean[t] = m;
        srstd[t] = rsqrtf(v + 1e-5f);
    }
    __syncthreads();

    const int hh = (h - 4) & 63;
    const int cl = t & 63, tq = t >> 6;
    for (int tb = 0; tb < 64; tb += 4) {
        int tok2 = tb + tq;
        int ww = (tok2 - 4) & 63;
        int win = b * 64 + (hh >> 3) * 8 + (ww >> 3);
        int n = (hh & 7) * 8 + (ww & 7);
        size_t orow = ((size_t)win * 64 + n) * 384;
        float m = smean[tok2], r = srstd[tok2];
        #pragma unroll
        for (int cb = 0; cb < 384; cb += 64) {
            int c = cb + cl;
            float v = base[(size_t)c * 4096 + tok2];
            g_ln1[orow + c] = (v - m) * r * gamma[c] + beta[c];
        }
    }
}

// ---------------------------------------------------------------------------
// TF32 tensor-core GEMM v2: C[M,N] = A[M,K] @ W[K,N] + bias (+ optional GELU)
// 256x128 block tile, BK=16, 256 threads = 8 warps (4m x 2n), warp 64x64.
// 1.0 LDS per MMA (af 16 + bf 16 LDS per 32 mmas). Double-buffered dynamic
// smem. A: [m][k] stride 20; B: [k][n] stride 136 (both conflict-free).
// ---------------------------------------------------------------------------
template<int SRC, int DST, int N, int K, int EPI>
__global__ void __launch_bounds__(256) tgemm_kernel(const float* __restrict__ W,
                                                    const float* __restrict__ bias) {
    extern __shared__ float smem[];
    float* As = smem;                 // 2 bufs x 256*20
    float* Bs = smem + 2 * 256 * 20;  // 2 bufs x 16*136
    const float* A    = gbuf<SRC>();
    float*       Cout = gbuf<DST>();

    const int bm = blockIdx.y << 8;
    const int bn = blockIdx.x << 7;
    const int t    = threadIdx.x;
    const int warp = t >> 5, lane = t & 31;
    const int wm = warp >> 1;          // 0..3 -> m offset wm*64
    const int wn = warp & 1;           // 0..1 -> n offset wn*64
    const int gid = lane >> 2, tig = lane & 3;

    // global A: 256 rows x 16 cols; thread loads float4 at rows rowA + 64*i
    const int rowA = t >> 2;           // 0..63
    const int colv = (t & 3) << 2;     // 0,4,8,12
    const float* Ap = A + (size_t)(bm + rowA) * K + colv;
    // global B: 16 rows x 128 cols; thread loads float4 at (rowB, colB), (rowB+8, colB)
    const int rowB = t >> 5;           // 0..7
    const int colB = (t & 31) << 2;
    const float* Bp = W + (size_t)rowB * N + bn + colB;

    float acc[4][8][4];
    #pragma unroll
    for (int mt = 0; mt < 4; ++mt)
        #pragma unroll
        for (int nt = 0; nt < 8; ++nt)
            #pragma unroll
            for (int r = 0; r < 4; ++r) acc[mt][nt][r] = 0.f;

    float4 ag[4], bg[2];
    #pragma unroll
    for (int i = 0; i < 4; ++i) ag[i] = *(const float4*)(Ap + (size_t)(64 * i) * K);
    bg[0] = *(const float4*)Bp;
    bg[1] = *(const float4*)(Bp + (size_t)8 * N);

    auto stage = [&](int buf) {
        float* Ab = As + buf * (256 * 20);
        #pragma unroll
        for (int i = 0; i < 4; ++i) {
            unsigned* ap = (unsigned*)&Ab[(rowA + 64 * i) * 20 + colv];
            *(uint4*)ap = make_uint4(f2tf(ag[i].x), f2tf(ag[i].y), f2tf(ag[i].z), f2tf(ag[i].w));
        }
        float* Bb = Bs + buf * (16 * 136);
        unsigned* bp0 = (unsigned*)&Bb[rowB * 136 + colB];
        unsigned* bp1 = (unsigned*)&Bb[(rowB + 8) * 136 + colB];
        *(uint4*)bp0 = make_uint4(f2tf(bg[0].x), f2tf(bg[0].y), f2tf(bg[0].z), f2tf(bg[0].w));
        *(uint4*)bp1 = make_uint4(f2tf(bg[1].x), f2tf(bg[1].y), f2tf(bg[1].z), f2tf(bg[1].w));
    };

    stage(0);
    __syncthreads();

    constexpr int NIT = K / 16;
    int cur = 0;
    for (int it = 0; it < NIT; ++it) {
        if (it + 1 < NIT) {
            Ap += 16;
            Bp += (size_t)16 * N;
            #pragma unroll
            for (int i = 0; i < 4; ++i) ag[i] = *(const float4*)(Ap + (size_t)(64 * i) * K);
            bg[0] = *(const float4*)Bp;
            bg[1] = *(const float4*)(Bp + (size_t)8 * N);
        }
        const unsigned* Asp = (const unsigned*)(As + cur * (256 * 20));
        const unsigned* Bsp = (const unsigned*)(Bs + cur * (16 * 136));
        #pragma unroll
        for (int ks = 0; ks < 16; ks += 8) {
            unsigned af[4][4], bf[8][2];
            #pragma unroll
            for (int mt = 0; mt < 4; ++mt) {
                int m0 = wm * 64 + mt * 16 + gid;
                af[mt][0] = Asp[m0 * 20 + ks + tig];
                af[mt][1] = Asp[(m0 + 8) * 20 + ks + tig];
                af[mt][2] = Asp[m0 * 20 + ks + tig + 4];
                af[mt][3] = Asp[(m0 + 8) * 20 + ks + tig + 4];
            }
            #pragma unroll
            for (int nt = 0; nt < 8; ++nt) {
                int n0 = wn * 64 + nt * 8 + gid;
                bf[nt][0] = Bsp[(ks + tig) * 136 + n0];
                bf[nt][1] = Bsp[(ks + tig + 4) * 136 + n0];
            }
            #pragma unroll
            for (int mt = 0; mt < 4; ++mt)
                #pragma unroll
                for (int nt = 0; nt < 8; ++nt)
                    mma_tf32(acc[mt][nt], af[mt], bf[nt]);
        }
        if (it + 1 < NIT) stage(cur ^ 1);
        __syncthreads();
        cur ^= 1;
    }

    // epilogue
    #pragma unroll
    for (int mt = 0; mt < 4; ++mt) {
        int mrow = bm + wm * 64 + mt * 16 + gid;
        #pragma unroll
        for (int nt = 0; nt < 8; ++nt) {
            int n = bn + wn * 64 + nt * 8 + tig * 2;
            float bvx = bias[n], bvy = bias[n + 1];
            float v0 = acc[mt][nt][0] + bvx;
            float v1 = acc[mt][nt][1] + bvy;
            float v2 = acc[mt][nt][2] + bvx;
            float v3 = acc[mt][nt][3] + bvy;
            if (EPI == 1) {
                v0 = 0.5f * v0 * (1.0f + erff(v0 * 0.70710678118654752f));
                v1 = 0.5f * v1 * (1.0f + erff(v1 * 0.70710678118654752f));
                v2 = 0.5f * v2 * (1.0f + erff(v2 * 0.70710678118654752f));
                v3 = 0.5f * v3 * (1.0f + erff(v3 * 0.70710678118654752f));
            }
            *(float2*)&Cout[(size_t)mrow * N + n]       = make_float2(v0, v1);
            *(float2*)&Cout[(size_t)(mrow + 8) * N + n] = make_float2(v2, v3);
        }
    }
}

static constexpr int TG_SMEM = (2 * 256 * 20 + 2 * 16 * 136) * 4;  // 58368 B

// ---------------------------------------------------------------------------
// Kernel 3: windowed attention (unchanged). One block per (win, head).
// ---------------------------------------------------------------------------
__global__ void __launch_bounds__(256) attn_kernel() {
    __shared__ float qs[64][49];
    __shared__ float ks[64][49];
    __shared__ float vs[64][49];
    const int blk = blockIdx.x;
    const int win = blk >> 3, head = blk & 7;
    const int t = threadIdx.x;

    for (int idx = t; idx < 64 * 48; idx += 256) {
        int n = idx / 48, d = idx - n * 48;
        size_t row = ((size_t)win * 64 + n) * 1152 + head * 48 + d;
        qs[n][d] = g_qkv[row];
        ks[n][d] = g_qkv[row + 384];
        vs[n][d] = g_qkv[row + 768];
    }
    __syncthreads();

    const int i  = t >> 2;
    const int q4 = t & 3;

    float vals[16];
    float rmax = -1e30f;
    #pragma unroll
    for (int jj = 0; jj < 16; ++jj) {
        int j = q4 * 16 + jj;
        float s = 0.f;
        #pragma unroll
        for (int d = 0; d < 48; ++d) s = fmaf(qs[i][d], ks[j][d], s);
        s *= 0.14433756729740643f;
        vals[jj] = s;
        rmax = fmaxf(rmax, s);
    }
    rmax = fmaxf(rmax, __shfl_xor_sync(0xffffffffu, rmax, 1));
    rmax = fmaxf(rmax, __shfl_xor_sync(0xffffffffu, rmax, 2));

    float rsum = 0.f;
    #pragma unroll
    for (int jj = 0; jj < 16; ++jj) {
        vals[jj] = expf(vals[jj] - rmax);
        rsum += vals[jj];
    }
    rsum += __shfl_xor_sync(0xffffffffu, rsum, 1);
    rsum += __shfl_xor_sync(0xffffffffu, rsum, 2);
    const float inv = 1.0f / rsum;

    float o[48];
    #pragma unroll
    for (int d = 0; d < 48; ++d) o[d] = 0.f;
    #pragma unroll
    for (int jj = 0; jj < 16; ++jj) {
        float a = vals[jj] * inv;
        int m = q4 * 16 + jj;
        #pragma unroll
        for (int d = 0; d < 48; ++d) o[d] = fmaf(a, vs[m][d], o[d]);
    }
    #pragma unroll
    for (int d = 0; d < 48; ++d) {
        o[d] += __shfl_xor_sync(0xffffffffu, o[d], 1);
        o[d] += __shfl_xor_sync(0xffffffffu, o[d], 2);
    }

    if (q4 == 0) {
        int b   = win >> 6;
        int wh  = (win >> 3) & 7;
        int wwn = win & 7;
        int hh  = ((wh  << 3) + (i >> 3) + 4) & 63;
        int ww  = ((wwn << 3) + (i & 7)  + 4) & 63;
        size_t nat = (size_t)b * 4096 + hh * 64 + ww;
        float* op = g_att + nat * 384 + head * 48;
        #pragma unroll
        for (int d = 0; d < 48; d += 4)
            *(float4*)&op[d] = *(float4*)&o[d];
    }
}

// ---------------------------------------------------------------------------
// Kernel 5: LayerNorm2 (unchanged)
// ---------------------------------------------------------------------------
__global__ void __launch_bounds__(256) ln2_kernel(const float* __restrict__ gamma,
                                                  const float* __restrict__ beta) {
    const int row  = blockIdx.x * 8 + (threadIdx.x >> 5);
    const int lane = threadIdx.x & 31;
    const float* in = g_xc + (size_t)row * 384;
    float v[12];
    float s = 0.f, q = 0.f;
    #pragma unroll
    for (int k = 0; k < 12; ++k) {
        v[k] = in[lane + k * 32];
        s += v[k]; q += v[k] * v[k];
    }
    #pragma unroll
    for (int o = 16; o; o >>= 1) {
        s += __shfl_xor_sync(0xffffffffu, s, o);
        q += __shfl_xor_sync(0xffffffffu, q, o);
    }
    float m = s * (1.f / 384.f);
    float var = q * (1.f / 384.f) - m * m;
    float r = rsqrtf(var + 1e-5f);
    float* out = g_ln2 + (size_t)row * 384;
    #pragma unroll
    for (int k = 0; k < 12; ++k) {
        int c = lane + k * 32;
        out[c] = (v[k] - m) * r * gamma[c] + beta[c];
    }
}

// ---------------------------------------------------------------------------
// Kernel 8: out[b,c,h,w] = xc[tok,c] + t[tok,c]  (tiled transpose + add)
// ---------------------------------------------------------------------------
__global__ void transadd_kernel(float* __restrict__ out) {
    __shared__ float tile[32][33];
    const int b  = blockIdx.z;
    const int c0 = blockIdx.x << 5;
    const int p0 = blockIdx.y << 5;
    const int tx = threadIdx.x, ty = threadIdx.y;
    #pragma unroll
    for (int j = 0; j < 32; j += 8) {
        size_t row = (size_t)b * 4096 + p0 + ty + j;
        size_t idx = row * 384 + c0 + tx;
        tile[ty + j][tx] = g_xc[idx] + g_t[idx];
    }
    __syncthreads();
    #pragma unroll
    for (int j = 0; j < 32; j += 8) {
        int c = c0 + ty + j;
        out[((size_t)b * 384 + c) * 4096 + p0 + tx] = tile[tx][ty + j];
    }
}

// ---------------------------------------------------------------------------
extern "C" void kernel_launch(void* const* d_in, const int* in_sizes, int n_in,
                              void* d_out, int out_size) {
    const float* x    = (const float*)d_in[0];
    const float* n1g  = (const float*)d_in[1];
    const float* n1b  = (const float*)d_in[2];
    const float* qkvw = (const float*)d_in[3];
    const float* qkvb = (const float*)d_in[4];
    const float* pw   = (const float*)d_in[5];
    const float* pb   = (const float*)d_in[6];
    const float* n2g  = (const float*)d_in[7];
    const float* n2b  = (const float*)d_in[8];
    const float* w1   = (const float*)d_in[9];
    const float* b1   = (const float*)d_in[10];
    const float* w2   = (const float*)d_in[11];
    const float* b2   = (const float*)d_in[12];
    float* out = (float*)d_out;

    // raise dynamic smem limit for all tgemm instantiations (idempotent)
    cudaFuncSetAttribute(tgemm_kernel<0, 1, 1152, 384, 0>,
                         cudaFuncAttributeMaxDynamicSharedMemorySize, TG_SMEM);
    cudaFuncSetAttribute(tgemm_kernel<2, 3, 384, 384, 0>,
                         cudaFuncAttributeMaxDynamicSharedMemorySize, TG_SMEM);
    cudaFuncSetAttribute(tgemm_kernel<4, 5, 1536, 384, 1>,
                         cudaFuncAttributeMaxDynamicSharedMemorySize, TG_SMEM);
    cudaFuncSetAttribute(tgemm_kernel<5, 6, 384, 1536, 0>,
                         cudaFuncAttributeMaxDynamicSharedMemorySize, TG_SMEM);

    // 1) shift + window partition + LN1  -> g_ln1 (window-ordered)
    ln1_kernel<<<1024, 256>>>(x, n1g, n1b);

    // 2) QKV GEMM: (65536x384) @ (384x1152) -> g_qkv
    tgemm_kernel<0, 1, 1152, 384, 0><<<dim3(9, 256), 256, TG_SMEM>>>(qkvw, qkvb);

    // 3) window attention -> g_att (natural token order)
    attn_kernel<<<8192, 256>>>();

    // 4) proj GEMM: (65536x384) @ (384x384) -> g_xc
    tgemm_kernel<2, 3, 384, 384, 0><<<dim3(3, 256), 256, TG_SMEM>>>(pw, pb);

    // 5) LN2 -> g_ln2
    ln2_kernel<<<8192, 256>>>(n2g, n2b);

    // 6) MLP1 GEMM + GELU: (65536x384) @ (384x1536) -> g_hid
    tgemm_kernel<4, 5, 1536, 384, 1><<<dim3(12, 256), 256, TG_SMEM>>>(w1, b1);

    // 7) MLP2 GEMM: (65536x1536) @ (1536x384) -> g_t
    tgemm_kernel<5, 6, 384, 1536, 0><<<dim3(3, 256), 256, TG_SMEM>>>(w2, b2);

    // 8) out = xc + t, transposed to (B,C,H,W)
    transadd_kernel<<<dim3(12, 128, 16), dim3(32, 8)>>>(out);
}

// round 9
// speedup vs baseline: 1.2429x; 1.2429x over previous
#include <cuda_runtime.h>
#include <math.h>

// ---------------------------------------------------------------------------
// SwinTransformerBlock  B=16, C=384, H=W=64, WS=8, SHIFT=4, HEADS=8, hd=48
// Round 9: 128x128 tile + 4-stage cp.async pipeline; tf32 rounding moved to
// producers (bit-identical math to round 6).
// ---------------------------------------------------------------------------

// Scratch (device globals; no runtime allocation)
__device__ float g_ln1[25165824];    // 65536*384   LN1 output, window-ordered (tf32-rounded)
__device__ float g_qkv[75497472];    // 65536*1152  QKV output (fp32)
__device__ float g_att[25165824];    // 65536*384   attn output, NATURAL order (tf32-rounded)
__device__ float g_xc [25165824];    // 65536*384   proj output (fp32)
__device__ float g_ln2[25165824];    // 65536*384   LN2 output (tf32-rounded)
__device__ float g_hid[100663296];   // 65536*1536  MLP hidden (tf32-rounded)
__device__ float g_t  [25165824];    // 65536*384   MLP output (fp32)
__device__ float g_w  [1769472];     // converted weights: qkv|proj|w1|w2

template<int ID> __device__ __forceinline__ float* gbuf();
template<> __device__ __forceinline__ float* gbuf<0>() { return g_ln1; }
template<> __device__ __forceinline__ float* gbuf<1>() { return g_qkv; }
template<> __device__ __forceinline__ float* gbuf<2>() { return g_att; }
template<> __device__ __forceinline__ float* gbuf<3>() { return g_xc;  }
template<> __device__ __forceinline__ float* gbuf<4>() { return g_ln2; }
template<> __device__ __forceinline__ float* gbuf<5>() { return g_hid; }
template<> __device__ __forceinline__ float* gbuf<6>() { return g_t;   }

static constexpr int WOFF_QKV = 0;
static constexpr int WOFF_PROJ = 442368;
static constexpr int WOFF_W1 = 589824;
static constexpr int WOFF_W2 = 1179648;

__device__ __forceinline__ float tf32r(float f) {
    unsigned u;
    asm("cvt.rna.tf32.f32 %0, %1;" : "=r"(u) : "f"(f));
    return __uint_as_float(u);
}

__device__ __forceinline__ void mma_tf32(float c[4], const unsigned a[4], const unsigned b[2]) {
    asm volatile(
        "mma.sync.aligned.m16n8k8.row.col.f32.tf32.tf32.f32 "
        "{%0,%1,%2,%3}, {%4,%5,%6,%7}, {%8,%9}, {%0,%1,%2,%3};"
        : "+f"(c[0]), "+f"(c[1]), "+f"(c[2]), "+f"(c[3])
        : "r"(a[0]), "r"(a[1]), "r"(a[2]), "r"(a[3]), "r"(b[0]), "r"(b[1]));
}

__device__ __forceinline__ void cp_async16(void* smem_dst, const void* gsrc) {
    unsigned dst = (unsigned)__cvta_generic_to_shared(smem_dst);
    asm volatile("cp.async.cg.shared.global [%0], [%1], 16;" :: "r"(dst), "l"(gsrc));
}
#define CP_COMMIT asm volatile("cp.async.commit_group;")
#define CP_WAIT(n) asm volatile("cp.async.wait_group %0;" :: "n"(n))

// ---------------------------------------------------------------------------
// Weight conversion: dst[i] = tf32_round(src[i]), vectorized by float4.
// ---------------------------------------------------------------------------
__global__ void wconv_kernel(const float* __restrict__ src, float* __restrict__ dst, int n4) {
    int i = blockIdx.x * 256 + threadIdx.x;
    if (i < n4) {
        float4 v = ((const float4*)src)[i];
        ((float4*)dst)[i] = make_float4(tf32r(v.x), tf32r(v.y), tf32r(v.z), tf32r(v.w));
    }
}

// ---------------------------------------------------------------------------
// Kernel 1: shift + window partition + LayerNorm1 (stores tf32-rounded)
// ---------------------------------------------------------------------------
__global__ void __launch_bounds__(256) ln1_kernel(const float* __restrict__ x,
                                                  const float* __restrict__ gamma,
                                                  const float* __restrict__ beta) {
    const int bh = blockIdx.x;
    const int b = bh >> 6, h = bh & 63;
    const int t = threadIdx.x;
    const int tok = t & 63, grp = t >> 6;
    const float* base = x + (size_t)b * 384 * 4096 + h * 64;

    float s = 0.f, q = 0.f;
    for (int c = grp * 96; c < grp * 96 + 96; ++c) {
        float v = base[(size_t)c * 4096 + tok];
        s += v; q += v * v;
    }
    __shared__ float ssum[4][64], ssq[4][64];
    __shared__ float smean[64], srstd[64];
    ssum[grp][tok] = s; ssq[grp][tok] = q;
    __syncthreads();
    if (t < 64) {
        float S = ssum[0][t] + ssum[1][t] + ssum[2][t] + ssum[3][t];
        float Q = ssq [0][t] + ssq [1][t] + ssq [2][t] + ssq [3][t];
        float m = S * (1.f / 384.f);
        float v = Q * (1.f / 384.f) - m * m;
        smean[t] = m;
        srstd[t] = rsqrtf(v + 1e-5f);
    }
    __syncthreads();

    const int hh = (h - 4) & 63;
    const int cl = t & 63, tq = t >> 6;
    for (int tb = 0; tb < 64; tb += 4) {
        int tok2 = tb + tq;
        int ww = (tok2 - 4) & 63;
        int win = b * 64 + (hh >> 3) * 8 + (ww >> 3);
        int n = (hh & 7) * 8 + (ww & 7);
        size_t orow = ((size_t)win * 64 + n) * 384;
        float m = smean[tok2], r = srstd[tok2];
        #pragma unroll
        for (int cb = 0; cb < 384; cb += 64) {
            int c = cb + cl;
            float v = base[(size_t)c * 4096 + tok2];
            g_ln1[orow + c] = tf32r((v - m) * r * gamma[c] + beta[c]);
        }
    }
}

// ---------------------------------------------------------------------------
// TF32 tensor-core GEMM v3: C[M,N] = A[M,K] @ W[K,N] + bias (+ optional GELU)
// 128x128 block tile, BK=16, 256 threads = 8 warps (4m x 2n), warp 32x64.
// 4-stage cp.async pipeline; inputs already tf32-rounded in gmem.
// A smem: [m][k] stride 20; B smem: [k][n] stride 136 (conflict-free LDS).
// ---------------------------------------------------------------------------
template<int SRC, int DST, int N, int K, int EPI>
__global__ void __launch_bounds__(256, 2) tgemm_kernel(const float* __restrict__ W,
                                                       const float* __restrict__ bias) {
    constexpr int STAGES = 4;
    constexpr int ASZ = 128 * 20;
    constexpr int BSZ = 16 * 136;
    extern __shared__ float smem[];
    float* As = smem;                   // STAGES * ASZ
    float* Bs = smem + STAGES * ASZ;    // STAGES * BSZ
    const float* A    = gbuf<SRC>();
    float*       Cout = gbuf<DST>();

    const int bm = blockIdx.y << 7;
    const int bn = blockIdx.x << 7;
    const int t    = threadIdx.x;
    const int warp = t >> 5, lane = t & 31;
    const int wm = warp >> 1;          // m offset wm*32
    const int wn = warp & 1;           // n offset wn*64
    const int gid = lane >> 2, tig = lane & 3;

    const int rowA = t >> 2;           // 0..63  (A tile: 128 rows x 16 cols)
    const int colv = (t & 3) << 2;     // 0,4,8,12
    const int rowB = t >> 5;           // 0..7   (B tile: 16 rows x 128 cols)
    const int colB = (t & 31) << 2;
    const float* ApBase = A + (size_t)(bm + rowA) * K + colv;
    const float* BpBase = W + (size_t)rowB * N + bn + colB;

    auto load_stage = [&](int buf, int koff) {
        float* Ab = As + buf * ASZ;
        cp_async16(&Ab[rowA * 20 + colv],        ApBase + koff);
        cp_async16(&Ab[(rowA + 64) * 20 + colv], ApBase + (size_t)64 * K + koff);
        float* Bb = Bs + buf * BSZ;
        const float* Bp = BpBase + (size_t)koff * N;
        cp_async16(&Bb[rowB * 136 + colB],       Bp);
        cp_async16(&Bb[(rowB + 8) * 136 + colB], Bp + (size_t)8 * N);
    };

    float acc[2][8][4];
    #pragma unroll
    for (int mt = 0; mt < 2; ++mt)
        #pragma unroll
        for (int nt = 0; nt < 8; ++nt)
            #pragma unroll
            for (int r = 0; r < 4; ++r) acc[mt][nt][r] = 0.f;

    constexpr int NIT = K / 16;

    #pragma unroll
    for (int s = 0; s < STAGES - 1; ++s) {
        load_stage(s, s * 16);
        CP_COMMIT;
    }

    int cur = 0;
    for (int it = 0; it < NIT; ++it) {
        CP_WAIT(STAGES - 2);
        __syncthreads();
        const unsigned* Asp = (const unsigned*)(As + cur * ASZ);
        const unsigned* Bsp = (const unsigned*)(Bs + cur * BSZ);
        #pragma unroll
        for (int ks = 0; ks < 16; ks += 8) {
            unsigned af[2][4], bf[8][2];
            #pragma unroll
            for (int mt = 0; mt < 2; ++mt) {
                int m0 = wm * 32 + mt * 16 + gid;
                af[mt][0] = Asp[m0 * 20 + ks + tig];
                af[mt][1] = Asp[(m0 + 8) * 20 + ks + tig];
                af[mt][2] = Asp[m0 * 20 + ks + tig + 4];
                af[mt][3] = Asp[(m0 + 8) * 20 + ks + tig + 4];
            }
            #pragma unroll
            for (int nt = 0; nt < 8; ++nt) {
                int n0 = wn * 64 + nt * 8 + gid;
                bf[nt][0] = Bsp[(ks + tig) * 136 + n0];
                bf[nt][1] = Bsp[(ks + tig + 4) * 136 + n0];
            }
            #pragma unroll
            for (int mt = 0; mt < 2; ++mt)
                #pragma unroll
                for (int nt = 0; nt < 8; ++nt)
                    mma_tf32(acc[mt][nt], af[mt], bf[nt]);
        }
        // Issue load for stage (it + STAGES - 1); overwrites the buffer used
        // at iter it-1 — safe: every warp passed this iter's __syncthreads,
        // which is after its iter it-1 compute.
        int nxt = it + STAGES - 1;
        if (nxt < NIT) load_stage((cur + STAGES - 1) % STAGES, nxt * 16);
        CP_COMMIT;   // commit every iter (possibly empty) to keep wait counts aligned
        cur = (cur + 1) % STAGES;
    }

    // epilogue
    #pragma unroll
    for (int mt = 0; mt < 2; ++mt) {
        int mrow = bm + wm * 32 + mt * 16 + gid;
        #pragma unroll
        for (int nt = 0; nt < 8; ++nt) {
            int n = bn + wn * 64 + nt * 8 + tig * 2;
            float bvx = bias[n], bvy = bias[n + 1];
            float v0 = acc[mt][nt][0] + bvx;
            float v1 = acc[mt][nt][1] + bvy;
            float v2 = acc[mt][nt][2] + bvx;
            float v3 = acc[mt][nt][3] + bvy;
            if (EPI == 1) {
                v0 = tf32r(0.5f * v0 * (1.0f + erff(v0 * 0.70710678118654752f)));
                v1 = tf32r(0.5f * v1 * (1.0f + erff(v1 * 0.70710678118654752f)));
                v2 = tf32r(0.5f * v2 * (1.0f + erff(v2 * 0.70710678118654752f)));
                v3 = tf32r(0.5f * v3 * (1.0f + erff(v3 * 0.70710678118654752f)));
            }
            *(float2*)&Cout[(size_t)mrow * N + n]       = make_float2(v0, v1);
            *(float2*)&Cout[(size_t)(mrow + 8) * N + n] = make_float2(v2, v3);
        }
    }
}

static constexpr int TG_SMEM = (4 * 128 * 20 + 4 * 16 * 136) * 4;  // 75776 B

// ---------------------------------------------------------------------------
// Kernel 3: windowed attention (stores tf32-rounded). One block per (win, head).
// ---------------------------------------------------------------------------
__global__ void __launch_bounds__(256) attn_kernel() {
    __shared__ float qs[64][49];
    __shared__ float ks[64][49];
    __shared__ float vs[64][49];
    const int blk = blockIdx.x;
    const int win = blk >> 3, head = blk & 7;
    const int t = threadIdx.x;

    for (int idx = t; idx < 64 * 48; idx += 256) {
        int n = idx / 48, d = idx - n * 48;
        size_t row = ((size_t)win * 64 + n) * 1152 + head * 48 + d;
        qs[n][d] = g_qkv[row];
        ks[n][d] = g_qkv[row + 384];
        vs[n][d] = g_qkv[row + 768];
    }
    __syncthreads();

    const int i  = t >> 2;
    const int q4 = t & 3;

    float vals[16];
    float rmax = -1e30f;
    #pragma unroll
    for (int jj = 0; jj < 16; ++jj) {
        int j = q4 * 16 + jj;
        float s = 0.f;
        #pragma unroll
        for (int d = 0; d < 48; ++d) s = fmaf(qs[i][d], ks[j][d], s);
        s *= 0.14433756729740643f;
        vals[jj] = s;
        rmax = fmaxf(rmax, s);
    }
    rmax = fmaxf(rmax, __shfl_xor_sync(0xffffffffu, rmax, 1));
    rmax = fmaxf(rmax, __shfl_xor_sync(0xffffffffu, rmax, 2));

    float rsum = 0.f;
    #pragma unroll
    for (int jj = 0; jj < 16; ++jj) {
        vals[jj] = expf(vals[jj] - rmax);
        rsum += vals[jj];
    }
    rsum += __shfl_xor_sync(0xffffffffu, rsum, 1);
    rsum += __shfl_xor_sync(0xffffffffu, rsum, 2);
    const float inv = 1.0f / rsum;

    float o[48];
    #pragma unroll
    for (int d = 0; d < 48; ++d) o[d] = 0.f;
    #pragma unroll
    for (int jj = 0; jj < 16; ++jj) {
        float a = vals[jj] * inv;
        int m = q4 * 16 + jj;
        #pragma unroll
        for (int d = 0; d < 48; ++d) o[d] = fmaf(a, vs[m][d], o[d]);
    }
    #pragma unroll
    for (int d = 0; d < 48; ++d) {
        o[d] += __shfl_xor_sync(0xffffffffu, o[d], 1);
        o[d] += __shfl_xor_sync(0xffffffffu, o[d], 2);
    }

    if (q4 == 0) {
        int b   = win >> 6;
        int wh  = (win >> 3) & 7;
        int wwn = win & 7;
        int hh  = ((wh  << 3) + (i >> 3) + 4) & 63;
        int ww  = ((wwn << 3) + (i & 7)  + 4) & 63;
        size_t nat = (size_t)b * 4096 + hh * 64 + ww;
        float* op = g_att + nat * 384 + head * 48;
        #pragma unroll
        for (int d = 0; d < 48; d += 4) {
            float4 v = *(float4*)&o[d];
            *(float4*)&op[d] = make_float4(tf32r(v.x), tf32r(v.y), tf32r(v.z), tf32r(v.w));
        }
    }
}

// ---------------------------------------------------------------------------
// Kernel 5: LayerNorm2 (stores tf32-rounded)
// ---------------------------------------------------------------------------
__global__ void __launch_bounds__(256) ln2_kernel(const float* __restrict__ gamma,
                                                  const float* __restrict__ beta) {
    const int row  = blockIdx.x * 8 + (threadIdx.x >> 5);
    const int lane = threadIdx.x & 31;
    const float* in = g_xc + (size_t)row * 384;
    float v[12];
    float s = 0.f, q = 0.f;
    #pragma unroll
    for (int k = 0; k < 12; ++k) {
        v[k] = in[lane + k * 32];
        s += v[k]; q += v[k] * v[k];
    }
    #pragma unroll
    for (int o = 16; o; o >>= 1) {
        s += __shfl_xor_sync(0xffffffffu, s, o);
        q += __shfl_xor_sync(0xffffffffu, q, o);
    }
    float m = s * (1.f / 384.f);
    float var = q * (1.f / 384.f) - m * m;
    float r = rsqrtf(var + 1e-5f);
    float* out = g_ln2 + (size_t)row * 384;
    #pragma unroll
    for (int k = 0; k < 12; ++k) {
        int c = lane + k * 32;
        out[c] = tf32r((v[k] - m) * r * gamma[c] + beta[c]);
    }
}

// ---------------------------------------------------------------------------
// Kernel 8: out[b,c,h,w] = xc[tok,c] + t[tok,c]  (tiled transpose + add)
// ---------------------------------------------------------------------------
__global__ void transadd_kernel(float* __restrict__ out) {
    __shared__ float tile[32][33];
    const int b  = blockIdx.z;
    const int c0 = blockIdx.x << 5;
    const int p0 = blockIdx.y << 5;
    const int tx = threadIdx.x, ty = threadIdx.y;
    #pragma unroll
    for (int j = 0; j < 32; j += 8) {
        size_t row = (size_t)b * 4096 + p0 + ty + j;
        size_t idx = row * 384 + c0 + tx;
        tile[ty + j][tx] = g_xc[idx] + g_t[idx];
    }
    __syncthreads();
    #pragma unroll
    for (int j = 0; j < 32; j += 8) {
        int c = c0 + ty + j;
        out[((size_t)b * 384 + c) * 4096 + p0 + tx] = tile[tx][ty + j];
    }
}

// ---------------------------------------------------------------------------
extern "C" void kernel_launch(void* const* d_in, const int* in_sizes, int n_in,
                              void* d_out, int out_size) {
    const float* x    = (const float*)d_in[0];
    const float* n1g  = (const float*)d_in[1];
    const float* n1b  = (const float*)d_in[2];
    const float* qkvw = (const float*)d_in[3];
    const float* qkvb = (const float*)d_in[4];
    const float* pw   = (const float*)d_in[5];
    const float* pb   = (const float*)d_in[6];
    const float* n2g  = (const float*)d_in[7];
    const float* n2b  = (const float*)d_in[8];
    const float* w1   = (const float*)d_in[9];
    const float* b1   = (const float*)d_in[10];
    const float* w2   = (const float*)d_in[11];
    const float* b2   = (const float*)d_in[12];
    float* out = (float*)d_out;

    cudaFuncSetAttribute(tgemm_kernel<0, 1, 1152, 384, 0>,
                         cudaFuncAttributeMaxDynamicSharedMemorySize, TG_SMEM);
    cudaFuncSetAttribute(tgemm_kernel<2, 3, 384, 384, 0>,
                         cudaFuncAttributeMaxDynamicSharedMemorySize, TG_SMEM);
    cudaFuncSetAttribute(tgemm_kernel<4, 5, 1536, 384, 1>,
                         cudaFuncAttributeMaxDynamicSharedMemorySize, TG_SMEM);
    cudaFuncSetAttribute(tgemm_kernel<5, 6, 384, 1536, 0>,
                         cudaFuncAttributeMaxDynamicSharedMemorySize, TG_SMEM);

    float* gw;
    cudaGetSymbolAddress((void**)&gw, g_w);

    // 0) weight tf32 pre-conversion (tiny)
    wconv_kernel<<<432, 256>>>(qkvw, gw + WOFF_QKV, 442368 / 4);
    wconv_kernel<<<144, 256>>>(pw,   gw + WOFF_PROJ, 147456 / 4);
    wconv_kernel<<<576, 256>>>(w1,   gw + WOFF_W1,  589824 / 4);
    wconv_kernel<<<576, 256>>>(w2,   gw + WOFF_W2,  589824 / 4);

    // 1) shift + window partition + LN1  -> g_ln1 (window-ordered, tf32-rounded)
    ln1_kernel<<<1024, 256>>>(x, n1g, n1b);

    // 2) QKV GEMM: (65536x384) @ (384x1152) -> g_qkv
    tgemm_kernel<0, 1, 1152, 384, 0><<<dim3(9, 512), 256, TG_SMEM>>>(gw + WOFF_QKV, qkvb);

    // 3) window attention -> g_att (natural token order, tf32-rounded)
    attn_kernel<<<8192, 256>>>();

    // 4) proj GEMM: (65536x384) @ (384x384) -> g_xc
    tgemm_kernel<2, 3, 384, 384, 0><<<dim3(3, 512), 256, TG_SMEM>>>(gw + WOFF_PROJ, pb);

    // 5) LN2 -> g_ln2 (tf32-rounded)
    ln2_kernel<<<8192, 256>>>(n2g, n2b);

    // 6) MLP1 GEMM + GELU: (65536x384) @ (384x1536) -> g_hid (tf32-rounded)
    tgemm_kernel<4, 5, 1536, 384, 1><<<dim3(12, 512), 256, TG_SMEM>>>(gw + WOFF_W1, b1);

    // 7) MLP2 GEMM: (65536x1536) @ (1536x384) -> g_t
    tgemm_kernel<5, 6, 384, 1536, 0><<<dim3(3, 512), 256, TG_SMEM>>>(gw + WOFF_W2, b2);

    // 8) out = xc + t, transposed to (B,C,H,W)
    transadd_kernel<<<dim3(12, 128, 16), dim3(32, 8)>>>(out);
}